// round 3
// baseline (speedup 1.0000x reference)
#include <cuda_runtime.h>
#include <math.h>
#include <stdint.h>

// ---------------- problem constants ----------------
#define SEQ   4096
#define HID   2048
#define NH    16
#define NKV   4
#define DH    128
#define BLKQ  64
#define NBLK  64
#define MSK   32
#define KTOP  8

#define NEGV  (-1000000000.0f)

// ---------------- scratch (device globals; no allocation allowed) ----------------
__device__ float g_q[SEQ * HID];            // roped q, layout [s][h*128+d]
__device__ float g_k[SEQ * (NKV * DH)];     // roped k, layout [s][kvh*128+d]
__device__ float g_v[SEQ * (NKV * DH)];     // v,       layout [s][kvh*128+d]
__device__ float g_attn[SEQ * HID];         // attention output [s][h*128+d]
__device__ float g_Sq[NH * NBLK * MSK];
__device__ float g_Sk[NKV * NBLK * MSK];
__device__ int   g_topk[NH * NBLK * KTOP];
__device__ float g_cos[SEQ * 64];
__device__ float g_sin[SEQ * 64];
__device__ double g_invf[64];

// ---------------- tf32 helpers ----------------
__device__ __forceinline__ uint32_t f2tf32(float x) {
    uint32_t u;
    asm("cvt.rna.tf32.f32 %0, %1;" : "=r"(u) : "f"(x));
    return u;
}

__device__ __forceinline__ void mma_tf32(float c[4],
    uint32_t a0, uint32_t a1, uint32_t a2, uint32_t a3,
    uint32_t b0, uint32_t b1)
{
    asm volatile(
        "mma.sync.aligned.m16n8k8.row.col.f32.tf32.tf32.f32 "
        "{%0,%1,%2,%3}, {%4,%5,%6,%7}, {%8,%9}, {%0,%1,%2,%3};"
        : "+f"(c[0]), "+f"(c[1]), "+f"(c[2]), "+f"(c[3])
        : "r"(a0), "r"(a1), "r"(a2), "r"(a3), "r"(b0), "r"(b1));
}

// ---------------- split-tf32 GEMM: C[M,N] = A[M,K] @ B[K,N], fp32-accurate ----------------
// CTA tile 128x128, BK=16, 256 threads (8 warps, warp tile 64x32).
// Each fp32 value is split into hi+lo tf32; 3 MMA passes (hh, hl, lh) give ~fp32 accuracy.
#define BK 16
#define AS_STRIDE 20    // mod 32 == 4  -> conflict-free A fragment loads
#define BS_STRIDE 136   // mod 32 == 8  -> conflict-free B fragment loads

__global__ __launch_bounds__(256, 2) void gemm_tf32_kernel(
    const float* __restrict__ A, const float* __restrict__ B, float* __restrict__ C,
    int M, int N, int K)
{
    __shared__ uint32_t AsH[128][AS_STRIDE];
    __shared__ uint32_t AsL[128][AS_STRIDE];
    __shared__ uint32_t BsH[BK][BS_STRIDE];
    __shared__ uint32_t BsL[BK][BS_STRIDE];

    int bx = blockIdx.x * 128;   // N offset
    int by = blockIdx.y * 128;   // M offset
    int t    = threadIdx.x;
    int warp = t >> 5;
    int lane = t & 31;
    int g   = lane >> 2;         // group id 0..7
    int tig = lane & 3;          // thread in group 0..3

    int warp_m = (warp & 1) * 64;
    int warp_n = (warp >> 1) * 32;

    float acc[4][4][4];          // [m_tile][n_tile][reg]
#pragma unroll
    for (int mt = 0; mt < 4; mt++)
#pragma unroll
        for (int nt = 0; nt < 4; nt++)
#pragma unroll
            for (int r = 0; r < 4; r++) acc[mt][nt][r] = 0.0f;

    for (int kt = 0; kt < K; kt += BK) {
        // load A tile 128x16, split hi/lo
#pragma unroll
        for (int l = 0; l < 2; l++) {
            int lin = t + l * 256;       // 0..511
            int r   = lin >> 2;          // 0..127
            int c4  = (lin & 3) * 4;     // 0,4,8,12
            float4 a = *(const float4*)&A[(size_t)(by + r) * K + kt + c4];
            float av[4] = {a.x, a.y, a.z, a.w};
#pragma unroll
            for (int u = 0; u < 4; u++) {
                uint32_t hi = f2tf32(av[u]);
                uint32_t lo = f2tf32(av[u] - __uint_as_float(hi));
                AsH[r][c4 + u] = hi;
                AsL[r][c4 + u] = lo;
            }
        }
        // load B tile 16x128, split hi/lo
#pragma unroll
        for (int l = 0; l < 2; l++) {
            int lin = t + l * 256;       // 0..511
            int r   = lin >> 5;          // 0..15
            int c4  = (lin & 31) * 4;    // 0..124
            float4 b = *(const float4*)&B[(size_t)(kt + r) * N + bx + c4];
            float bv[4] = {b.x, b.y, b.z, b.w};
#pragma unroll
            for (int u = 0; u < 4; u++) {
                uint32_t hi = f2tf32(bv[u]);
                uint32_t lo = f2tf32(bv[u] - __uint_as_float(hi));
                BsH[r][c4 + u] = hi;
                BsL[r][c4 + u] = lo;
            }
        }
        __syncthreads();

#pragma unroll
        for (int k8 = 0; k8 < BK; k8 += 8) {
            uint32_t ah[4][4], bh[4][2], bl[4][2];
#pragma unroll
            for (int nt = 0; nt < 4; nt++) {
                int col = warp_n + nt * 8 + g;
                bh[nt][0] = BsH[k8 + tig][col];
                bh[nt][1] = BsH[k8 + tig + 4][col];
                bl[nt][0] = BsL[k8 + tig][col];
                bl[nt][1] = BsL[k8 + tig + 4][col];
            }
#pragma unroll
            for (int mt = 0; mt < 4; mt++) {
                int row = warp_m + mt * 16 + g;
                ah[mt][0] = AsH[row][k8 + tig];
                ah[mt][1] = AsH[row + 8][k8 + tig];
                ah[mt][2] = AsH[row][k8 + tig + 4];
                ah[mt][3] = AsH[row + 8][k8 + tig + 4];
            }
            // hi * hi
#pragma unroll
            for (int mt = 0; mt < 4; mt++)
#pragma unroll
                for (int nt = 0; nt < 4; nt++)
                    mma_tf32(acc[mt][nt], ah[mt][0], ah[mt][1], ah[mt][2], ah[mt][3],
                             bh[nt][0], bh[nt][1]);
            // hi * lo
#pragma unroll
            for (int mt = 0; mt < 4; mt++)
#pragma unroll
                for (int nt = 0; nt < 4; nt++)
                    mma_tf32(acc[mt][nt], ah[mt][0], ah[mt][1], ah[mt][2], ah[mt][3],
                             bl[nt][0], bl[nt][1]);
            // lo * hi (reload A as lo)
#pragma unroll
            for (int mt = 0; mt < 4; mt++) {
                int row = warp_m + mt * 16 + g;
                ah[mt][0] = AsL[row][k8 + tig];
                ah[mt][1] = AsL[row + 8][k8 + tig];
                ah[mt][2] = AsL[row][k8 + tig + 4];
                ah[mt][3] = AsL[row + 8][k8 + tig + 4];
            }
#pragma unroll
            for (int mt = 0; mt < 4; mt++)
#pragma unroll
                for (int nt = 0; nt < 4; nt++)
                    mma_tf32(acc[mt][nt], ah[mt][0], ah[mt][1], ah[mt][2], ah[mt][3],
                             bh[nt][0], bh[nt][1]);
        }
        __syncthreads();
    }

    // epilogue
#pragma unroll
    for (int mt = 0; mt < 4; mt++) {
#pragma unroll
        for (int nt = 0; nt < 4; nt++) {
            int row = by + warp_m + mt * 16 + g;
            int col = bx + warp_n + nt * 8 + 2 * tig;
            *(float2*)&C[(size_t)row * N + col]       = make_float2(acc[mt][nt][0], acc[mt][nt][1]);
            *(float2*)&C[(size_t)(row + 8) * N + col] = make_float2(acc[mt][nt][2], acc[mt][nt][3]);
        }
    }
}

// ---------------- RoPE inv_freq table (fp64 pow, 64 threads once) ----------------
__global__ void invf_kernel()
{
    int j = threadIdx.x;
    g_invf[j] = pow(10000.0, -(double)(2 * j) / 128.0);
}

// ---------------- RoPE cos/sin table: fp64 angle + mod 2pi, float sincos ----------------
__global__ void rope_table_kernel(const int* __restrict__ pos)
{
    int s = blockIdx.x;
    int j = threadIdx.x;  // 0..63
    double ang = (double)pos[s] * g_invf[j];
    double r = fmod(ang, 6.283185307179586476925286766559);
    float sv, cv;
    sincosf((float)r, &sv, &cv);
    g_cos[s * 64 + j] = cv;
    g_sin[s * 64 + j] = sv;
}

// ---------------- RoPE in place: grid (S, nheads), 128 threads ----------------
__global__ void rope_kernel(float* __restrict__ buf, int stride)
{
    int s = blockIdx.x;
    int h = blockIdx.y;
    int d = threadIdx.x;
    __shared__ float row[DH];
    float x = buf[(size_t)s * stride + h * DH + d];
    row[d] = x;
    __syncthreads();
    float part = (d < 64) ? -row[d + 64] : row[d - 64];
    float c  = g_cos[s * 64 + (d & 63)];
    float sn = g_sin[s * 64 + (d & 63)];
    buf[(size_t)s * stride + h * DH + d] = x * c + part * sn;
}

// ---------------- sketch: S[h][n][m] = mean_r( buf[n*64+r] ) @ H  ----------------
__global__ void sketch_kernel(const float* __restrict__ buf, const float* __restrict__ Hm,
                              float* __restrict__ Sout, int stride)
{
    int n = blockIdx.x;   // block index
    int h = blockIdx.y;   // head
    int d = threadIdx.x;  // 0..127
    __shared__ float mv[DH];
    float sum = 0.0f;
#pragma unroll 8
    for (int r = 0; r < BLKQ; r++)
        sum += buf[(size_t)(n * BLKQ + r) * stride + h * DH + d];
    mv[d] = sum * (1.0f / 64.0f);
    __syncthreads();
    if (d < MSK) {
        float acc = 0.0f;
#pragma unroll 8
        for (int dd = 0; dd < DH; dd++)
            acc += mv[dd] * Hm[dd * MSK + d];
        Sout[(h * NBLK + n) * MSK + d] = acc;
    }
}

// ---------------- block-score + top-k selection: grid (NBLK, NH), 64 threads ----------------
__global__ void topk_kernel()
{
    int i = blockIdx.x;   // query block
    int h = blockIdx.y;   // head
    int j = threadIdx.x;  // candidate key block
    __shared__ float bs[NBLK];

    float val;
    if (j > i) {
        val = NEGV;
    } else {
        const float* sq = &g_Sq[(h * NBLK + i) * MSK];
        const float* sk = &g_Sk[((h >> 2) * NBLK + j) * MSK];
        float acc = 0.0f;
#pragma unroll
        for (int m = 0; m < MSK; m++) acc += sq[m] * sk[m];
        val = acc;
    }
    if (j == i) val = 1000000000.0f;
    bs[j] = val;
    __syncthreads();

    if (j == 0) {
        // 8 passes of argmax, lowest index wins ties (matches jax.lax.top_k)
        for (int t = 0; t < KTOP; t++) {
            float best = -INFINITY;
            int bi = 0;
            for (int c = 0; c < NBLK; c++) {
                if (bs[c] > best) { best = bs[c]; bi = c; }
            }
            g_topk[(h * NBLK + i) * KTOP + t] = bi;
            bs[bi] = -INFINITY;
        }
    }
}

// ---------------- sparse flash attention: grid (NBLK, NH), 256 threads ----------------
#define ATT_SMEM_FLOATS (128 * 65 + 128 * 65 + 64 * 65 + 3 * 64)
#define ATT_SMEM_BYTES  (ATT_SMEM_FLOATS * 4)

__global__ __launch_bounds__(256) void attn_kernel()
{
    extern __shared__ float sm[];
    float* QsT = sm;                    // [dd][r]  stride 65
    float* KVs = QsT + 128 * 65;        // [dd][c]  stride 65 (K, then reused for V)
    float* Ps  = KVs + 128 * 65;        // [r][c]   stride 65
    float* m_s = Ps + 64 * 65;
    float* l_s = m_s + 64;
    float* a_s = l_s + 64;

    int i   = blockIdx.x;    // query block
    int h   = blockIdx.y;    // head
    int kvh = h >> 2;
    int t   = threadIdx.x;
    int ty  = t >> 4;        // 0..15
    int tx  = t & 15;        // 0..15

    const float scale = 0.088388347648318447f;  // 1/sqrt(128)

    for (int idx = t; idx < BLKQ * DH; idx += 256) {
        int r  = idx >> 7;
        int dd = idx & 127;
        QsT[dd * 65 + r] = g_q[(size_t)(i * BLKQ + r) * HID + h * DH + dd] * scale;
    }
    if (t < 64) { m_s[t] = -INFINITY; l_s[t] = 0.0f; }

    float O[4][8];
#pragma unroll
    for (int ii = 0; ii < 4; ii++)
#pragma unroll
        for (int jj = 0; jj < 8; jj++) O[ii][jj] = 0.0f;

    __syncthreads();

    for (int kb = 0; kb < KTOP; kb++) {
        int j = g_topk[(h * NBLK + i) * KTOP + kb];

        for (int idx = t; idx < BLKQ * DH; idx += 256) {
            int c  = idx >> 7;
            int dd = idx & 127;
            KVs[dd * 65 + c] = g_k[(size_t)(j * BLKQ + c) * (NKV * DH) + kvh * DH + dd];
        }
        __syncthreads();

        float acc[4][4];
#pragma unroll
        for (int ii = 0; ii < 4; ii++)
#pragma unroll
            for (int jj = 0; jj < 4; jj++) acc[ii][jj] = 0.0f;

#pragma unroll 8
        for (int dd = 0; dd < DH; dd++) {
            float qv[4], kv[4];
#pragma unroll
            for (int ii = 0; ii < 4; ii++) qv[ii] = QsT[dd * 65 + ty * 4 + ii];
#pragma unroll
            for (int jj = 0; jj < 4; jj++) kv[jj] = KVs[dd * 65 + tx * 4 + jj];
#pragma unroll
            for (int ii = 0; ii < 4; ii++)
#pragma unroll
                for (int jj = 0; jj < 4; jj++) acc[ii][jj] += qv[ii] * kv[jj];
        }

#pragma unroll
        for (int ii = 0; ii < 4; ii++) {
            int r = ty * 4 + ii;
            int qpos = i * BLKQ + r;
#pragma unroll
            for (int jj = 0; jj < 4; jj++) {
                int c = tx * 4 + jj;
                int kpos = j * BLKQ + c;
                Ps[r * 65 + c] = (kpos <= qpos) ? acc[ii][jj] : NEGV;
            }
        }
        __syncthreads();

        if (t < 64) {
            int r = t;
            float rmax = -INFINITY;
#pragma unroll 8
            for (int c = 0; c < BLKQ; c++) rmax = fmaxf(rmax, Ps[r * 65 + c]);
            float mo = m_s[r];
            float mn = fmaxf(mo, rmax);
            float al = expf(mo - mn);
            float sum = 0.0f;
#pragma unroll 8
            for (int c = 0; c < BLKQ; c++) {
                float p = expf(Ps[r * 65 + c] - mn);
                Ps[r * 65 + c] = p;
                sum += p;
            }
            l_s[r] = l_s[r] * al + sum;
            m_s[r] = mn;
            a_s[r] = al;
        }
        __syncthreads();

        float alr[4];
#pragma unroll
        for (int ii = 0; ii < 4; ii++) alr[ii] = a_s[ty * 4 + ii];
#pragma unroll
        for (int ii = 0; ii < 4; ii++)
#pragma unroll
            for (int jj = 0; jj < 8; jj++) O[ii][jj] *= alr[ii];

        for (int idx = t; idx < BLKQ * DH; idx += 256) {
            int c    = idx >> 7;
            int dcol = idx & 127;
            KVs[dcol * 65 + c] = g_v[(size_t)(j * BLKQ + c) * (NKV * DH) + kvh * DH + dcol];
        }
        __syncthreads();

#pragma unroll 4
        for (int c = 0; c < BLKQ; c++) {
            float pr[4];
#pragma unroll
            for (int ii = 0; ii < 4; ii++) pr[ii] = Ps[(ty * 4 + ii) * 65 + c];
            float pv[8];
#pragma unroll
            for (int jj = 0; jj < 4; jj++) {
                pv[jj]     = KVs[(tx * 4 + jj) * 65 + c];
                pv[4 + jj] = KVs[(64 + tx * 4 + jj) * 65 + c];
            }
#pragma unroll
            for (int ii = 0; ii < 4; ii++)
#pragma unroll
                for (int jj = 0; jj < 8; jj++) O[ii][jj] += pr[ii] * pv[jj];
        }
        __syncthreads();
    }

    float linv[4];
#pragma unroll
    for (int ii = 0; ii < 4; ii++) linv[ii] = 1.0f / l_s[ty * 4 + ii];
#pragma unroll
    for (int ii = 0; ii < 4; ii++) {
        int r = i * BLKQ + ty * 4 + ii;
#pragma unroll
        for (int jj = 0; jj < 8; jj++) {
            int col = (jj < 4) ? (tx * 4 + jj) : (64 + tx * 4 + jj - 4);
            g_attn[(size_t)r * HID + h * DH + col] = O[ii][jj] * linv[ii];
        }
    }
}

// ---------------- launch ----------------
extern "C" void kernel_launch(void* const* d_in, const int* in_sizes, int n_in,
                              void* d_out, int out_size)
{
    const float* hs  = (const float*)d_in[0];
    const int*   pos = (const int*)d_in[1];
    const float* Wq  = (const float*)d_in[2];
    const float* Wk  = (const float*)d_in[3];
    const float* Wv  = (const float*)d_in[4];
    const float* Wo  = (const float*)d_in[5];
    const float* Hm  = (const float*)d_in[6];
    float* out = (float*)d_out;

    float *q, *k, *v, *attn, *Sq, *Sk;
    cudaGetSymbolAddress((void**)&q,    g_q);
    cudaGetSymbolAddress((void**)&k,    g_k);
    cudaGetSymbolAddress((void**)&v,    g_v);
    cudaGetSymbolAddress((void**)&attn, g_attn);
    cudaGetSymbolAddress((void**)&Sq,   g_Sq);
    cudaGetSymbolAddress((void**)&Sk,   g_Sk);

    // QKV projections (split-tf32 tensor-core GEMM, fp32-accurate)
    gemm_tf32_kernel<<<dim3(HID / 128, SEQ / 128), 256>>>(hs, Wq, q, SEQ, HID, HID);
    gemm_tf32_kernel<<<dim3((NKV * DH) / 128, SEQ / 128), 256>>>(hs, Wk, k, SEQ, NKV * DH, HID);
    gemm_tf32_kernel<<<dim3((NKV * DH) / 128, SEQ / 128), 256>>>(hs, Wv, v, SEQ, NKV * DH, HID);

    // RoPE
    invf_kernel<<<1, 64>>>();
    rope_table_kernel<<<SEQ, 64>>>(pos);
    rope_kernel<<<dim3(SEQ, NH), DH>>>(q, HID);
    rope_kernel<<<dim3(SEQ, NKV), DH>>>(k, NKV * DH);

    // sketches
    sketch_kernel<<<dim3(NBLK, NH), DH>>>(q, Hm, Sq, HID);
    sketch_kernel<<<dim3(NBLK, NKV), DH>>>(k, Hm, Sk, NKV * DH);

    // block scores + top-k
    topk_kernel<<<dim3(NBLK, NH), 64>>>();

    // sparse attention
    cudaFuncSetAttribute(attn_kernel, cudaFuncAttributeMaxDynamicSharedMemorySize, ATT_SMEM_BYTES);
    attn_kernel<<<dim3(NBLK, NH), 256, ATT_SMEM_BYTES>>>();

    // output projection
    gemm_tf32_kernel<<<dim3(HID / 128, SEQ / 128), 256>>>(attn, Wo, out, SEQ, HID, HID);
}

// round 5
// speedup vs baseline: 1.4385x; 1.4385x over previous
#include <cuda_runtime.h>
#include <math.h>
#include <stdint.h>

// ---------------- problem constants ----------------
#define SEQ   4096
#define HID   2048
#define NH    16
#define NKV   4
#define DH    128
#define BLKQ  64
#define NBLK  64
#define MSK   32
#define KTOP  8
#define QKVN  3072          // fused QKV output columns (2048 q | 512 k | 512 v)

#define NEGV  (-1000000000.0f)

// ---------------- scratch (device globals; no allocation allowed) ----------------
__device__ float g_qkv[SEQ * QKVN];        // fused q|k|v, layout [s][3072]
__device__ float g_wqkv[HID * QKVN];       // packed [Wq | Wk | Wv], [k][3072]
__device__ float g_attn[SEQ * HID];        // attention output [s][h*128+d]
__device__ float g_Sq[NH * NBLK * MSK];
__device__ float g_Sk[NKV * NBLK * MSK];
__device__ int   g_topk[NH * NBLK * KTOP];
__device__ float g_cos[SEQ * 64];
__device__ float g_sin[SEQ * 64];
__device__ double g_invf[64];

// ---------------- f32x2 helpers (Blackwell packed fp32 FMA: SASS FFMA2) ----------------
typedef unsigned long long u64;

__device__ __forceinline__ u64 pk2(float lo, float hi) {
    u64 r;
    asm("mov.b64 %0, {%1, %2};" : "=l"(r)
        : "r"(__float_as_uint(lo)), "r"(__float_as_uint(hi)));
    return r;
}
__device__ __forceinline__ u64 bc2(float x) { return pk2(x, x); }
__device__ __forceinline__ void upk2(u64 p, float& lo, float& hi) {
    uint32_t a, b;
    asm("mov.b64 {%0, %1}, %2;" : "=r"(a), "=r"(b) : "l"(p));
    lo = __uint_as_float(a);
    hi = __uint_as_float(b);
}
#define FMA2(acc, a, b) asm("fma.rn.f32x2 %0, %1, %2, %0;" : "+l"(acc) : "l"(a), "l"(b))
#define MUL2(acc, b)    asm("mul.rn.f32x2 %0, %0, %1;"     : "+l"(acc) : "l"(b))

// ---------------- f32x2 SGEMM: C[M,N] = A[M,K] @ B[K,N], row-major fp32 ----------------
// 128x128 tile, BK=16, 256 threads, 8x8 per thread, FFMA2 inner product.
__global__ __launch_bounds__(256, 2) void sgemm2_kernel(
    const float* __restrict__ A, const float* __restrict__ B, float* __restrict__ C,
    int M, int N, int K)
{
    __shared__ float As[16][128];   // transposed A tile: As[k][m]
    __shared__ float Bs[16][128];   // B tile: Bs[k][n]

    int bx = blockIdx.x * 128;      // N offset
    int by = blockIdx.y * 128;      // M offset
    int t  = threadIdx.x;
    int ty = t >> 4;                // 0..15
    int tx = t & 15;                // 0..15

    // acc2[p][j]: row-pair p (2 rows packed in f32x2 lanes) x col j
    u64 acc2[4][8];
#pragma unroll
    for (int p = 0; p < 4; p++)
#pragma unroll
        for (int j = 0; j < 8; j++) acc2[p][j] = 0ull;

    for (int kt = 0; kt < K; kt += 16) {
        // load A tile 128x16 (transposed into As)
#pragma unroll
        for (int l = 0; l < 2; l++) {
            int lin = t + l * 256;
            int r   = lin >> 2;
            int c4  = (lin & 3) * 4;
            float4 a = *(const float4*)&A[(size_t)(by + r) * K + kt + c4];
            As[c4 + 0][r] = a.x;
            As[c4 + 1][r] = a.y;
            As[c4 + 2][r] = a.z;
            As[c4 + 3][r] = a.w;
        }
        // load B tile 16x128
#pragma unroll
        for (int l = 0; l < 2; l++) {
            int lin = t + l * 256;
            int r   = lin >> 5;
            int c4  = (lin & 31) * 4;
            *(float4*)&Bs[r][c4] = *(const float4*)&B[(size_t)(kt + r) * N + bx + c4];
        }
        __syncthreads();

#pragma unroll
        for (int k = 0; k < 16; k++) {
            // row pairs direct from shared as 64-bit loads (8B aligned)
            u64 a01 = *(const u64*)&As[k][ty * 4];
            u64 a23 = *(const u64*)&As[k][ty * 4 + 2];
            u64 a45 = *(const u64*)&As[k][64 + ty * 4];
            u64 a67 = *(const u64*)&As[k][64 + ty * 4 + 2];
            float4 b0 = *(float4*)&Bs[k][tx * 4];
            float4 b1 = *(float4*)&Bs[k][64 + tx * 4];
            u64 bb[8];
            bb[0] = bc2(b0.x); bb[1] = bc2(b0.y); bb[2] = bc2(b0.z); bb[3] = bc2(b0.w);
            bb[4] = bc2(b1.x); bb[5] = bc2(b1.y); bb[6] = bc2(b1.z); bb[7] = bc2(b1.w);
#pragma unroll
            for (int j = 0; j < 8; j++) {
                FMA2(acc2[0][j], a01, bb[j]);
                FMA2(acc2[1][j], a23, bb[j]);
                FMA2(acc2[2][j], a45, bb[j]);
                FMA2(acc2[3][j], a67, bb[j]);
            }
        }
        __syncthreads();
    }

    // epilogue: unpack row pairs, 2 float4 stores per row
#pragma unroll
    for (int p = 0; p < 4; p++) {
        int rbase = by + ((p < 2) ? (ty * 4 + 2 * p) : (64 + ty * 4 + 2 * (p - 2)));
        float lo[8], hi[8];
#pragma unroll
        for (int j = 0; j < 8; j++) upk2(acc2[p][j], lo[j], hi[j]);
        *(float4*)&C[(size_t)rbase * N + bx + tx * 4] =
            make_float4(lo[0], lo[1], lo[2], lo[3]);
        *(float4*)&C[(size_t)rbase * N + bx + 64 + tx * 4] =
            make_float4(lo[4], lo[5], lo[6], lo[7]);
        *(float4*)&C[(size_t)(rbase + 1) * N + bx + tx * 4] =
            make_float4(hi[0], hi[1], hi[2], hi[3]);
        *(float4*)&C[(size_t)(rbase + 1) * N + bx + 64 + tx * 4] =
            make_float4(hi[4], hi[5], hi[6], hi[7]);
    }
}

// ---------------- pack [Wq | Wk | Wv] into one [2048 x 3072] B matrix ----------------
__global__ void pack_w_kernel(const float* __restrict__ Wq, const float* __restrict__ Wk,
                              const float* __restrict__ Wv)
{
    int r = blockIdx.y;
    int j = blockIdx.x * 256 + threadIdx.x;
    float v;
    if (j < 2048)      v = Wq[(size_t)r * 2048 + j];
    else if (j < 2560) v = Wk[(size_t)r * 512 + (j - 2048)];
    else               v = Wv[(size_t)r * 512 + (j - 2560)];
    g_wqkv[(size_t)r * QKVN + j] = v;
}

// ---------------- RoPE tables ----------------
__global__ void invf_kernel()
{
    int j = threadIdx.x;
    g_invf[j] = pow(10000.0, -(double)(2 * j) / 128.0);
}

__global__ void rope_table_kernel(const int* __restrict__ pos)
{
    int s = blockIdx.x;
    int j = threadIdx.x;  // 0..63
    double ang = (double)pos[s] * g_invf[j];
    double r = fmod(ang, 6.283185307179586476925286766559);
    float sv, cv;
    sincosf((float)r, &sv, &cv);
    g_cos[s * 64 + j] = cv;
    g_sin[s * 64 + j] = sv;
}

// ---------------- RoPE in place: grid (S, nheads), 128 threads ----------------
__global__ void rope_kernel(float* __restrict__ buf, int stride)
{
    int s = blockIdx.x;
    int h = blockIdx.y;
    int d = threadIdx.x;
    __shared__ float row[DH];
    float x = buf[(size_t)s * stride + h * DH + d];
    row[d] = x;
    __syncthreads();
    float part = (d < 64) ? -row[d + 64] : row[d - 64];
    float c  = g_cos[s * 64 + (d & 63)];
    float sn = g_sin[s * 64 + (d & 63)];
    buf[(size_t)s * stride + h * DH + d] = x * c + part * sn;
}

// ---------------- sketch ----------------
__global__ void sketch_kernel(const float* __restrict__ buf, const float* __restrict__ Hm,
                              float* __restrict__ Sout, int stride)
{
    int n = blockIdx.x;
    int h = blockIdx.y;
    int d = threadIdx.x;
    __shared__ float mv[DH];
    float sum = 0.0f;
#pragma unroll 8
    for (int r = 0; r < BLKQ; r++)
        sum += buf[(size_t)(n * BLKQ + r) * stride + h * DH + d];
    mv[d] = sum * (1.0f / 64.0f);
    __syncthreads();
    if (d < MSK) {
        float acc = 0.0f;
#pragma unroll 8
        for (int dd = 0; dd < DH; dd++)
            acc += mv[dd] * Hm[dd * MSK + d];
        Sout[(h * NBLK + n) * MSK + d] = acc;
    }
}

// ---------------- block-score + top-k ----------------
__global__ void topk_kernel()
{
    int i = blockIdx.x;
    int h = blockIdx.y;
    int j = threadIdx.x;
    __shared__ float bs[NBLK];

    float val;
    if (j > i) {
        val = NEGV;
    } else {
        const float* sq = &g_Sq[(h * NBLK + i) * MSK];
        const float* sk = &g_Sk[((h >> 2) * NBLK + j) * MSK];
        float acc = 0.0f;
#pragma unroll
        for (int m = 0; m < MSK; m++) acc += sq[m] * sk[m];
        val = acc;
    }
    if (j == i) val = 1000000000.0f;
    bs[j] = val;
    __syncthreads();

    if (j == 0) {
        for (int t = 0; t < KTOP; t++) {
            float best = -INFINITY;
            int bi = 0;
            for (int c = 0; c < NBLK; c++) {
                if (bs[c] > best) { best = bs[c]; bi = c; }
            }
            g_topk[(h * NBLK + i) * KTOP + t] = bi;
            bs[bi] = -INFINITY;
        }
    }
}

// ---------------- sparse flash attention (f32x2 inner loops) ----------------
// strides chosen for alignment: QsT/KVs stride 68 (16B-aligned rows), Ps stride 66
#define QS_STR 68
#define PS_STR 66
#define ATT_SMEM_FLOATS (128 * QS_STR + 128 * QS_STR + 64 * PS_STR + 3 * 64)
#define ATT_SMEM_BYTES  (ATT_SMEM_FLOATS * 4)

__global__ __launch_bounds__(256) void attn_kernel()
{
    extern __shared__ float sm[];
    float* QsT = sm;                        // [dd][r]  stride 68
    float* KVs = QsT + 128 * QS_STR;        // [dd][c]  stride 68 (K, then V)
    float* Ps  = KVs + 128 * QS_STR;        // [r][c]   stride 66
    float* m_s = Ps + 64 * PS_STR;
    float* l_s = m_s + 64;
    float* a_s = l_s + 64;

    int i   = blockIdx.x;
    int h   = blockIdx.y;
    int kvh = h >> 2;
    int t   = threadIdx.x;
    int ty  = t >> 4;
    int tx  = t & 15;

    const float scale = 0.088388347648318447f;  // 1/sqrt(128)

    for (int idx = t; idx < BLKQ * DH; idx += 256) {
        int r  = idx >> 7;
        int dd = idx & 127;
        QsT[dd * QS_STR + r] = g_qkv[(size_t)(i * BLKQ + r) * QKVN + h * DH + dd] * scale;
    }
    if (t < 64) { m_s[t] = -INFINITY; l_s[t] = 0.0f; }

    // O2[ii][jp]: row ii (4 rows), col-pair jp (pairs over j) in f32x2 lanes
    u64 O2[4][4];
#pragma unroll
    for (int ii = 0; ii < 4; ii++)
#pragma unroll
        for (int jp = 0; jp < 4; jp++) O2[ii][jp] = 0ull;

    __syncthreads();

    for (int kb = 0; kb < KTOP; kb++) {
        int j = g_topk[(h * NBLK + i) * KTOP + kb];

        for (int idx = t; idx < BLKQ * DH; idx += 256) {
            int c  = idx >> 7;
            int dd = idx & 127;
            KVs[dd * QS_STR + c] = g_qkv[(size_t)(j * BLKQ + c) * QKVN + 2048 + kvh * DH + dd];
        }
        __syncthreads();

        // scores: row-pairs from QsT (64-bit LDS), kv broadcast pairs; 8 FFMA2/dd
        u64 s2[2][4];
#pragma unroll
        for (int ip = 0; ip < 2; ip++)
#pragma unroll
            for (int jj = 0; jj < 4; jj++) s2[ip][jj] = 0ull;

#pragma unroll 8
        for (int dd = 0; dd < DH; dd++) {
            u64 q01 = *(const u64*)&QsT[dd * QS_STR + ty * 4];
            u64 q23 = *(const u64*)&QsT[dd * QS_STR + ty * 4 + 2];
            float4 kv = *(float4*)&KVs[dd * QS_STR + tx * 4];
            u64 kb0 = bc2(kv.x), kb1 = bc2(kv.y), kb2 = bc2(kv.z), kb3 = bc2(kv.w);
            FMA2(s2[0][0], q01, kb0); FMA2(s2[0][1], q01, kb1);
            FMA2(s2[0][2], q01, kb2); FMA2(s2[0][3], q01, kb3);
            FMA2(s2[1][0], q23, kb0); FMA2(s2[1][1], q23, kb1);
            FMA2(s2[1][2], q23, kb2); FMA2(s2[1][3], q23, kb3);
        }

        // unpack, mask (kpos <= qpos), store to Ps
        float acc[4][4];
#pragma unroll
        for (int jj = 0; jj < 4; jj++) {
            upk2(s2[0][jj], acc[0][jj], acc[1][jj]);
            upk2(s2[1][jj], acc[2][jj], acc[3][jj]);
        }
#pragma unroll
        for (int ii = 0; ii < 4; ii++) {
            int r = ty * 4 + ii;
            int qpos = i * BLKQ + r;
#pragma unroll
            for (int jj = 0; jj < 4; jj++) {
                int c = tx * 4 + jj;
                int kpos = j * BLKQ + c;
                Ps[r * PS_STR + c] = (kpos <= qpos) ? acc[ii][jj] : NEGV;
            }
        }
        __syncthreads();

        // online softmax per row (64 threads)
        if (t < 64) {
            int r = t;
            float rmax = -INFINITY;
#pragma unroll 8
            for (int c = 0; c < BLKQ; c++) rmax = fmaxf(rmax, Ps[r * PS_STR + c]);
            float mo = m_s[r];
            float mn = fmaxf(mo, rmax);
            float al = expf(mo - mn);
            float sum = 0.0f;
#pragma unroll 8
            for (int c = 0; c < BLKQ; c++) {
                float p = expf(Ps[r * PS_STR + c] - mn);
                Ps[r * PS_STR + c] = p;
                sum += p;
            }
            l_s[r] = l_s[r] * al + sum;
            m_s[r] = mn;
            a_s[r] = al;
        }
        __syncthreads();

        // rescale accumulator
#pragma unroll
        for (int ii = 0; ii < 4; ii++) {
            u64 alb = bc2(a_s[ty * 4 + ii]);
#pragma unroll
            for (int jp = 0; jp < 4; jp++) MUL2(O2[ii][jp], alb);
        }

        // load V block (VsT[dcol][c])
        for (int idx = t; idx < BLKQ * DH; idx += 256) {
            int c    = idx >> 7;
            int dcol = idx & 127;
            KVs[dcol * QS_STR + c] = g_qkv[(size_t)(j * BLKQ + c) * QKVN + 2560 + kvh * DH + dcol];
        }
        __syncthreads();

        // O += P @ V : pr broadcast pairs, pv col-pairs; 16 FFMA2/c
#pragma unroll 4
        for (int c = 0; c < BLKQ; c++) {
            u64 prb[4];
#pragma unroll
            for (int ii = 0; ii < 4; ii++) prb[ii] = bc2(Ps[(ty * 4 + ii) * PS_STR + c]);
            float v0 = KVs[(tx * 4 + 0) * QS_STR + c];
            float v1 = KVs[(tx * 4 + 1) * QS_STR + c];
            float v2 = KVs[(tx * 4 + 2) * QS_STR + c];
            float v3 = KVs[(tx * 4 + 3) * QS_STR + c];
            float v4 = KVs[(64 + tx * 4 + 0) * QS_STR + c];
            float v5 = KVs[(64 + tx * 4 + 1) * QS_STR + c];
            float v6 = KVs[(64 + tx * 4 + 2) * QS_STR + c];
            float v7 = KVs[(64 + tx * 4 + 3) * QS_STR + c];
            u64 vp0 = pk2(v0, v1), vp1 = pk2(v2, v3), vp2 = pk2(v4, v5), vp3 = pk2(v6, v7);
#pragma unroll
            for (int ii = 0; ii < 4; ii++) {
                FMA2(O2[ii][0], prb[ii], vp0);
                FMA2(O2[ii][1], prb[ii], vp1);
                FMA2(O2[ii][2], prb[ii], vp2);
                FMA2(O2[ii][3], prb[ii], vp3);
            }
        }
        __syncthreads();
    }

    // epilogue: divide by l, write out
#pragma unroll
    for (int ii = 0; ii < 4; ii++) {
        float linv = 1.0f / l_s[ty * 4 + ii];
        int r = i * BLKQ + ty * 4 + ii;
        float o[8];
        upk2(O2[ii][0], o[0], o[1]);
        upk2(O2[ii][1], o[2], o[3]);
        upk2(O2[ii][2], o[4], o[5]);
        upk2(O2[ii][3], o[6], o[7]);
        float* dst = &g_attn[(size_t)r * HID + h * DH];
        *(float4*)&dst[tx * 4]      = make_float4(o[0] * linv, o[1] * linv, o[2] * linv, o[3] * linv);
        *(float4*)&dst[64 + tx * 4] = make_float4(o[4] * linv, o[5] * linv, o[6] * linv, o[7] * linv);
    }
}

// ---------------- launch ----------------
extern "C" void kernel_launch(void* const* d_in, const int* in_sizes, int n_in,
                              void* d_out, int out_size)
{
    const float* hs  = (const float*)d_in[0];
    const int*   pos = (const int*)d_in[1];
    const float* Wq  = (const float*)d_in[2];
    const float* Wk  = (const float*)d_in[3];
    const float* Wv  = (const float*)d_in[4];
    const float* Wo  = (const float*)d_in[5];
    const float* Hm  = (const float*)d_in[6];
    float* out = (float*)d_out;

    float *qkv, *wqkv, *attn, *Sq, *Sk;
    cudaGetSymbolAddress((void**)&qkv,  g_qkv);
    cudaGetSymbolAddress((void**)&wqkv, g_wqkv);
    cudaGetSymbolAddress((void**)&attn, g_attn);
    cudaGetSymbolAddress((void**)&Sq,   g_Sq);
    cudaGetSymbolAddress((void**)&Sk,   g_Sk);

    // pack weights, fused QKV projection (f32x2 SGEMM)
    pack_w_kernel<<<dim3(QKVN / 256, HID), 256>>>(Wq, Wk, Wv);
    sgemm2_kernel<<<dim3(QKVN / 128, SEQ / 128), 256>>>(hs, wqkv, qkv, SEQ, QKVN, HID);

    // RoPE
    invf_kernel<<<1, 64>>>();
    rope_table_kernel<<<SEQ, 64>>>(pos);
    rope_kernel<<<dim3(SEQ, NH), DH>>>(qkv, QKVN);            // q columns [0,2048)
    rope_kernel<<<dim3(SEQ, NKV), DH>>>(qkv + 2048, QKVN);    // k columns [2048,2560)

    // sketches
    sketch_kernel<<<dim3(NBLK, NH), DH>>>(qkv, Hm, Sq, QKVN);
    sketch_kernel<<<dim3(NBLK, NKV), DH>>>(qkv + 2048, Hm, Sk, QKVN);

    // block scores + top-k
    topk_kernel<<<dim3(NBLK, NH), 64>>>();

    // sparse attention
    cudaFuncSetAttribute(attn_kernel, cudaFuncAttributeMaxDynamicSharedMemorySize, ATT_SMEM_BYTES);
    attn_kernel<<<dim3(NBLK, NH), 256, ATT_SMEM_BYTES>>>();

    // output projection (f32x2 SGEMM)
    sgemm2_kernel<<<dim3(HID / 128, SEQ / 128), 256>>>(attn, Wo, out, SEQ, HID, HID);
}

// round 7
// speedup vs baseline: 2.2957x; 1.5959x over previous
#include <cuda_runtime.h>
#include <cuda_fp16.h>
#include <math.h>
#include <stdint.h>

// ---------------- problem constants ----------------
#define SEQ   4096
#define HID   2048
#define NH    16
#define NKV   4
#define DH    128
#define BLKQ  64
#define NBLK  64
#define MSK   32
#define KTOP  8
#define QKVN  3072          // fused QKV output columns (2048 q | 512 k | 512 v)

#define NEGV  (-1000000000.0f)

// ---------------- scratch (device globals; no allocation allowed) ----------------
__device__ float  g_qkv[SEQ * QKVN];         // fused q|k|v fp32, layout [s][3072]
__device__ __half g_ha_hi[SEQ * HID];        // hidden_states hi plane [s][k]
__device__ __half g_ha_lo[SEQ * HID];        // hidden_states lo plane
__device__ __half2 g_wb_hi[(HID/2) * QKVN];  // packed W_qkv hi, k-pair interleaved [k2][n]
__device__ __half2 g_wb_lo[(HID/2) * QKVN];
__device__ __half g_oa_hi[SEQ * HID];        // attention-out hi plane [s][n]
__device__ __half g_oa_lo[SEQ * HID];
__device__ __half2 g_wob_hi[(HID/2) * HID];  // Wo hi, k-pair interleaved [k2][n]
__device__ __half2 g_wob_lo[(HID/2) * HID];
__device__ float  g_Sq[NH * NBLK * MSK];
__device__ float  g_Sk[NKV * NBLK * MSK];
__device__ int    g_topk[NH * NBLK * KTOP];
__device__ float  g_cos[SEQ * 64];
__device__ float  g_sin[SEQ * 64];
__device__ double g_invf[64];

// =======================================================================
// fp16 split GEMM (3-pass): C[M,N] = A[M,K] @ B[K,N], fp32-accurate
// CTA 128x128, BK=32, 256 threads, warp tile 64x32, m16n8k16 HMMA,
// cp.async double-buffered. A planes: fp16 row-major [M][K].
// B planes: half2 k-pair interleaved [K/2][N] (element (k2,n) = {B[2k2][n], B[2k2+1][n]}).
// =======================================================================

#define A_STR2 20                        // half2 per A smem row (16 data + 4 pad)
#define B_STR2 136                       // half2 per B smem k2-row (128 data + 8 pad)
#define A_PLANE_W (128 * A_STR2)         // words per A plane  (2560)
#define B_PLANE_W (16 * B_STR2)          // words per B plane  (2176)
#define STAGE_W   (2 * A_PLANE_W + 2 * B_PLANE_W)   // 9472 words = 37888 B
#define GEMM_SMEM_BYTES (2 * STAGE_W * 4)           // 75776 B

__device__ __forceinline__ uint32_t smem_u32(const void* p) {
    uint32_t a;
    asm("{ .reg .u64 t; cvta.to.shared.u64 t, %1; cvt.u32.u64 %0, t; }" : "=r"(a) : "l"(p));
    return a;
}
#define CP16(dst, src) \
    asm volatile("cp.async.cg.shared.global [%0], [%1], 16;" :: "r"(dst), "l"(src))
#define CP_COMMIT() asm volatile("cp.async.commit_group;")
#define CP_WAIT1()  asm volatile("cp.async.wait_group 1;")

__device__ __forceinline__ void mma16816(float c[4],
    uint32_t a0, uint32_t a1, uint32_t a2, uint32_t a3, uint32_t b0, uint32_t b1)
{
    asm volatile(
        "mma.sync.aligned.m16n8k16.row.col.f32.f16.f16.f32 "
        "{%0,%1,%2,%3}, {%4,%5,%6,%7}, {%8,%9}, {%0,%1,%2,%3};"
        : "+f"(c[0]), "+f"(c[1]), "+f"(c[2]), "+f"(c[3])
        : "r"(a0), "r"(a1), "r"(a2), "r"(a3), "r"(b0), "r"(b1));
}

__global__ __launch_bounds__(256, 2) void gemm_fp16_kernel(
    const __half* __restrict__ Ah, const __half* __restrict__ Al,
    const __half2* __restrict__ Bh, const __half2* __restrict__ Bl,
    float* __restrict__ C, int M, int N, int K)
{
    extern __shared__ uint32_t smw[];
    const uint32_t smb = smem_u32(smw);

    const int bx = blockIdx.x * 128;    // N offset
    const int by = blockIdx.y * 128;    // M offset
    const int tid  = threadIdx.x;
    const int warp = tid >> 5;
    const int lane = tid & 31;
    const int g    = lane >> 2;         // 0..7
    const int tig  = lane & 3;          // 0..3
    const int warp_m = (warp & 1) * 64;
    const int warp_n = (warp >> 1) * 32;

    const int NIT = K / 32;

    // per-thread load slots (8 x 16B chunks per stage)
    const int ar = tid >> 2;            // A row 0..63 handled twice (tid..+256)
    const int ac = (tid & 3) * 16;      // byte offset within A row (4 chunks of 16B per row)
    const int bk = tid >> 5;            // B k2-row 0..7 (+8 for second half)
    const int bn = (tid & 31) * 16;     // byte offset within B row data (512B per row)

    // returns nothing; issues 8 cp.async for stage s, k-chunk it
    auto load_stage = [&](int it, int s) {
        const int kt = it * 32;
        const uint32_t base = smb + (uint32_t)s * (STAGE_W * 4);
        // A planes: rows ar and ar+64, 4 chunks/row handled by (tid&3)
        {
            const char* sh = (const char*)(Ah + (size_t)(by + ar) * K + kt);
            const char* sl = (const char*)(Al + (size_t)(by + ar) * K + kt);
            CP16(base + ar * 80 + ac, sh + ac);
            CP16(base + A_PLANE_W * 4 + ar * 80 + ac, sl + ac);
            const char* sh2 = (const char*)(Ah + (size_t)(by + ar + 64) * K + kt);
            const char* sl2 = (const char*)(Al + (size_t)(by + ar + 64) * K + kt);
            CP16(base + (ar + 64) * 80 + ac, sh2 + ac);
            CP16(base + A_PLANE_W * 4 + (ar + 64) * 80 + ac, sl2 + ac);
        }
        // B planes: k2-rows bk and bk+8, 32 chunks/row handled by (tid&31)
        {
            const uint32_t bb = base + 2 * A_PLANE_W * 4;
            const char* sh = (const char*)(Bh + (size_t)(kt / 2 + bk) * N + bx);
            const char* sl = (const char*)(Bl + (size_t)(kt / 2 + bk) * N + bx);
            CP16(bb + bk * 544 + bn, sh + bn);
            CP16(bb + B_PLANE_W * 4 + bk * 544 + bn, sl + bn);
            const char* sh2 = (const char*)(Bh + (size_t)(kt / 2 + bk + 8) * N + bx);
            const char* sl2 = (const char*)(Bl + (size_t)(kt / 2 + bk + 8) * N + bx);
            CP16(bb + (bk + 8) * 544 + bn, sh2 + bn);
            CP16(bb + B_PLANE_W * 4 + (bk + 8) * 544 + bn, sl2 + bn);
        }
    };

    float acc[4][4][4];
#pragma unroll
    for (int mt = 0; mt < 4; mt++)
#pragma unroll
        for (int nt = 0; nt < 4; nt++)
#pragma unroll
            for (int r = 0; r < 4; r++) acc[mt][nt][r] = 0.0f;

    load_stage(0, 0); CP_COMMIT();
    load_stage(1, 1); CP_COMMIT();

    for (int it = 0; it < NIT; ++it) {
        CP_WAIT1();
        __syncthreads();

        const uint32_t* st = smw + (it & 1) * STAGE_W;
        const uint32_t* AH = st;
        const uint32_t* AL = st + A_PLANE_W;
        const uint32_t* BH = st + 2 * A_PLANE_W;
        const uint32_t* BL = BH + B_PLANE_W;

#pragma unroll
        for (int kk = 0; kk < 2; ++kk) {
            uint32_t a[4][4], bh[4][2], bl[4][2];
#pragma unroll
            for (int nt = 0; nt < 4; nt++) {
                int n = warp_n + nt * 8 + g;
                bh[nt][0] = BH[(kk * 8 + tig) * B_STR2 + n];
                bh[nt][1] = BH[(kk * 8 + tig + 4) * B_STR2 + n];
                bl[nt][0] = BL[(kk * 8 + tig) * B_STR2 + n];
                bl[nt][1] = BL[(kk * 8 + tig + 4) * B_STR2 + n];
            }
#pragma unroll
            for (int mt = 0; mt < 4; mt++) {
                int row = warp_m + mt * 16 + g;
                a[mt][0] = AH[row * A_STR2 + kk * 8 + tig];
                a[mt][1] = AH[(row + 8) * A_STR2 + kk * 8 + tig];
                a[mt][2] = AH[row * A_STR2 + kk * 8 + tig + 4];
                a[mt][3] = AH[(row + 8) * A_STR2 + kk * 8 + tig + 4];
            }
            // pass 1: hi * hi
#pragma unroll
            for (int mt = 0; mt < 4; mt++)
#pragma unroll
                for (int nt = 0; nt < 4; nt++)
                    mma16816(acc[mt][nt], a[mt][0], a[mt][1], a[mt][2], a[mt][3],
                             bh[nt][0], bh[nt][1]);
            // pass 2: hi * lo
#pragma unroll
            for (int mt = 0; mt < 4; mt++)
#pragma unroll
                for (int nt = 0; nt < 4; nt++)
                    mma16816(acc[mt][nt], a[mt][0], a[mt][1], a[mt][2], a[mt][3],
                             bl[nt][0], bl[nt][1]);
            // reload A as lo plane (reuse regs), pass 3: lo * hi
#pragma unroll
            for (int mt = 0; mt < 4; mt++) {
                int row = warp_m + mt * 16 + g;
                a[mt][0] = AL[row * A_STR2 + kk * 8 + tig];
                a[mt][1] = AL[(row + 8) * A_STR2 + kk * 8 + tig];
                a[mt][2] = AL[row * A_STR2 + kk * 8 + tig + 4];
                a[mt][3] = AL[(row + 8) * A_STR2 + kk * 8 + tig + 4];
            }
#pragma unroll
            for (int mt = 0; mt < 4; mt++)
#pragma unroll
                for (int nt = 0; nt < 4; nt++)
                    mma16816(acc[mt][nt], a[mt][0], a[mt][1], a[mt][2], a[mt][3],
                             bh[nt][0], bh[nt][1]);
        }
        __syncthreads();
        if (it + 2 < NIT) load_stage(it + 2, it & 1);
        CP_COMMIT();
    }

    // epilogue
#pragma unroll
    for (int mt = 0; mt < 4; mt++) {
#pragma unroll
        for (int nt = 0; nt < 4; nt++) {
            int row = by + warp_m + mt * 16 + g;
            int col = bx + warp_n + nt * 8 + 2 * tig;
            *(float2*)&C[(size_t)row * N + col]       = make_float2(acc[mt][nt][0], acc[mt][nt][1]);
            *(float2*)&C[(size_t)(row + 8) * N + col] = make_float2(acc[mt][nt][2], acc[mt][nt][3]);
        }
    }
}

// ---------------- operand prep kernels ----------------
// hidden_states -> fp16 hi/lo planes (row-major)
__global__ void split_a_kernel(const float* __restrict__ src)
{
    int i = blockIdx.x * 256 + threadIdx.x;
    float x = src[i];
    __half h = __float2half_rn(x);
    g_ha_hi[i] = h;
    g_ha_lo[i] = __float2half_rn(x - __half2float(h));
}

// [Wq|Wk|Wv] -> k-pair-interleaved half2 hi/lo planes
__global__ void pack_split_w_kernel(const float* __restrict__ Wq,
                                    const float* __restrict__ Wk,
                                    const float* __restrict__ Wv)
{
    int k2 = blockIdx.y;                       // 0..1023
    int j  = blockIdx.x * 256 + threadIdx.x;   // 0..3071
    const float* W; int col, width;
    if (j < 2048)      { W = Wq; col = j;        width = 2048; }
    else if (j < 2560) { W = Wk; col = j - 2048; width = 512;  }
    else               { W = Wv; col = j - 2560; width = 512;  }
    float x0 = W[(size_t)(2 * k2) * width + col];
    float x1 = W[(size_t)(2 * k2 + 1) * width + col];
    __half h0 = __float2half_rn(x0), h1 = __float2half_rn(x1);
    g_wb_hi[(size_t)k2 * QKVN + j] = __halves2half2(h0, h1);
    g_wb_lo[(size_t)k2 * QKVN + j] =
        __halves2half2(__float2half_rn(x0 - __half2float(h0)),
                       __float2half_rn(x1 - __half2float(h1)));
}

// Wo -> k-pair-interleaved half2 hi/lo planes
__global__ void split_wo_kernel(const float* __restrict__ Wo)
{
    int k2 = blockIdx.y;                       // 0..1023
    int n  = blockIdx.x * 256 + threadIdx.x;   // 0..2047
    float x0 = Wo[(size_t)(2 * k2) * HID + n];
    float x1 = Wo[(size_t)(2 * k2 + 1) * HID + n];
    __half h0 = __float2half_rn(x0), h1 = __float2half_rn(x1);
    g_wob_hi[(size_t)k2 * HID + n] = __halves2half2(h0, h1);
    g_wob_lo[(size_t)k2 * HID + n] =
        __halves2half2(__float2half_rn(x0 - __half2float(h0)),
                       __float2half_rn(x1 - __half2float(h1)));
}

// ---------------- RoPE tables ----------------
__global__ void invf_kernel()
{
    int j = threadIdx.x;
    g_invf[j] = pow(10000.0, -(double)(2 * j) / 128.0);
}

__global__ void rope_table_kernel(const int* __restrict__ pos)
{
    int s = blockIdx.x;
    int j = threadIdx.x;  // 0..63
    double ang = (double)pos[s] * g_invf[j];
    double r = fmod(ang, 6.283185307179586476925286766559);
    float sv, cv;
    sincosf((float)r, &sv, &cv);
    g_cos[s * 64 + j] = cv;
    g_sin[s * 64 + j] = sv;
}

// ---------------- RoPE in place: grid (S, nheads), 128 threads ----------------
__global__ void rope_kernel(float* __restrict__ buf, int stride)
{
    int s = blockIdx.x;
    int h = blockIdx.y;
    int d = threadIdx.x;
    __shared__ float row[DH];
    float x = buf[(size_t)s * stride + h * DH + d];
    row[d] = x;
    __syncthreads();
    float part = (d < 64) ? -row[d + 64] : row[d - 64];
    float c  = g_cos[s * 64 + (d & 63)];
    float sn = g_sin[s * 64 + (d & 63)];
    buf[(size_t)s * stride + h * DH + d] = x * c + part * sn;
}

// ---------------- sketch ----------------
__global__ void sketch_kernel(const float* __restrict__ buf, const float* __restrict__ Hm,
                              float* __restrict__ Sout, int stride)
{
    int n = blockIdx.x;
    int h = blockIdx.y;
    int d = threadIdx.x;
    __shared__ float mv[DH];
    float sum = 0.0f;
#pragma unroll 8
    for (int r = 0; r < BLKQ; r++)
        sum += buf[(size_t)(n * BLKQ + r) * stride + h * DH + d];
    mv[d] = sum * (1.0f / 64.0f);
    __syncthreads();
    if (d < MSK) {
        float acc = 0.0f;
#pragma unroll 8
        for (int dd = 0; dd < DH; dd++)
            acc += mv[dd] * Hm[dd * MSK + d];
        Sout[(h * NBLK + n) * MSK + d] = acc;
    }
}

// ---------------- block-score + top-k ----------------
__global__ void topk_kernel()
{
    int i = blockIdx.x;
    int h = blockIdx.y;
    int j = threadIdx.x;
    __shared__ float bs[NBLK];

    float val;
    if (j > i) {
        val = NEGV;
    } else {
        const float* sq = &g_Sq[(h * NBLK + i) * MSK];
        const float* sk = &g_Sk[((h >> 2) * NBLK + j) * MSK];
        float acc = 0.0f;
#pragma unroll
        for (int m = 0; m < MSK; m++) acc += sq[m] * sk[m];
        val = acc;
    }
    if (j == i) val = 1000000000.0f;
    bs[j] = val;
    __syncthreads();

    if (j == 0) {
        for (int t = 0; t < KTOP; t++) {
            float best = -INFINITY;
            int bi = 0;
            for (int c = 0; c < NBLK; c++) {
                if (bs[c] > best) { best = bs[c]; bi = c; }
            }
            g_topk[(h * NBLK + i) * KTOP + t] = bi;
            bs[bi] = -INFINITY;
        }
    }
}

// ---------------- sparse flash attention (epilogue writes fp16 split planes) ----------------
#define QS_STR 68
#define PS_STR 66
#define ATT_SMEM_FLOATS (128 * QS_STR + 128 * QS_STR + 64 * PS_STR + 3 * 64)
#define ATT_SMEM_BYTES  (ATT_SMEM_FLOATS * 4)

__global__ __launch_bounds__(256) void attn_kernel()
{
    extern __shared__ float sm[];
    float* QsT = sm;
    float* KVs = QsT + 128 * QS_STR;
    float* Ps  = KVs + 128 * QS_STR;
    float* m_s = Ps + 64 * PS_STR;
    float* l_s = m_s + 64;
    float* a_s = l_s + 64;

    int i   = blockIdx.x;
    int h   = blockIdx.y;
    int kvh = h >> 2;
    int t   = threadIdx.x;
    int ty  = t >> 4;
    int tx  = t & 15;

    const float scale = 0.088388347648318447f;  // 1/sqrt(128)

    for (int idx = t; idx < BLKQ * DH; idx += 256) {
        int r  = idx >> 7;
        int dd = idx & 127;
        QsT[dd * QS_STR + r] = g_qkv[(size_t)(i * BLKQ + r) * QKVN + h * DH + dd] * scale;
    }
    if (t < 64) { m_s[t] = -INFINITY; l_s[t] = 0.0f; }

    float O[4][8];
#pragma unroll
    for (int ii = 0; ii < 4; ii++)
#pragma unroll
        for (int jj = 0; jj < 8; jj++) O[ii][jj] = 0.0f;

    __syncthreads();

    for (int kb = 0; kb < KTOP; kb++) {
        int j = g_topk[(h * NBLK + i) * KTOP + kb];

        for (int idx = t; idx < BLKQ * DH; idx += 256) {
            int c  = idx >> 7;
            int dd = idx & 127;
            KVs[dd * QS_STR + c] = g_qkv[(size_t)(j * BLKQ + c) * QKVN + 2048 + kvh * DH + dd];
        }
        __syncthreads();

        float acc[4][4];
#pragma unroll
        for (int ii = 0; ii < 4; ii++)
#pragma unroll
            for (int jj = 0; jj < 4; jj++) acc[ii][jj] = 0.0f;

#pragma unroll 8
        for (int dd = 0; dd < DH; dd++) {
            float qv[4], kv[4];
#pragma unroll
            for (int ii = 0; ii < 4; ii++) qv[ii] = QsT[dd * QS_STR + ty * 4 + ii];
#pragma unroll
            for (int jj = 0; jj < 4; jj++) kv[jj] = KVs[dd * QS_STR + tx * 4 + jj];
#pragma unroll
            for (int ii = 0; ii < 4; ii++)
#pragma unroll
                for (int jj = 0; jj < 4; jj++) acc[ii][jj] += qv[ii] * kv[jj];
        }

#pragma unroll
        for (int ii = 0; ii < 4; ii++) {
            int r = ty * 4 + ii;
            int qpos = i * BLKQ + r;
#pragma unroll
            for (int jj = 0; jj < 4; jj++) {
                int c = tx * 4 + jj;
                int kpos = j * BLKQ + c;
                Ps[r * PS_STR + c] = (kpos <= qpos) ? acc[ii][jj] : NEGV;
            }
        }
        __syncthreads();

        if (t < 64) {
            int r = t;
            float rmax = -INFINITY;
#pragma unroll 8
            for (int c = 0; c < BLKQ; c++) rmax = fmaxf(rmax, Ps[r * PS_STR + c]);
            float mo = m_s[r];
            float mn = fmaxf(mo, rmax);
            float al = expf(mo - mn);
            float sum = 0.0f;
#pragma unroll 8
            for (int c = 0; c < BLKQ; c++) {
                float p = expf(Ps[r * PS_STR + c] - mn);
                Ps[r * PS_STR + c] = p;
                sum += p;
            }
            l_s[r] = l_s[r] * al + sum;
            m_s[r] = mn;
            a_s[r] = al;
        }
        __syncthreads();

        float alr[4];
#pragma unroll
        for (int ii = 0; ii < 4; ii++) alr[ii] = a_s[ty * 4 + ii];
#pragma unroll
        for (int ii = 0; ii < 4; ii++)
#pragma unroll
            for (int jj = 0; jj < 8; jj++) O[ii][jj] *= alr[ii];

        for (int idx = t; idx < BLKQ * DH; idx += 256) {
            int c    = idx >> 7;
            int dcol = idx & 127;
            KVs[dcol * QS_STR + c] = g_qkv[(size_t)(j * BLKQ + c) * QKVN + 2560 + kvh * DH + dcol];
        }
        __syncthreads();

#pragma unroll 4
        for (int c = 0; c < BLKQ; c++) {
            float pr[4];
#pragma unroll
            for (int ii = 0; ii < 4; ii++) pr[ii] = Ps[(ty * 4 + ii) * PS_STR + c];
            float pv[8];
#pragma unroll
            for (int jj = 0; jj < 4; jj++) {
                pv[jj]     = KVs[(tx * 4 + jj) * QS_STR + c];
                pv[4 + jj] = KVs[(64 + tx * 4 + jj) * QS_STR + c];
            }
#pragma unroll
            for (int ii = 0; ii < 4; ii++)
#pragma unroll
                for (int jj = 0; jj < 8; jj++) O[ii][jj] += pr[ii] * pv[jj];
        }
        __syncthreads();
    }

    // epilogue: divide by l, write fp16 split planes for the Wo GEMM
#pragma unroll
    for (int ii = 0; ii < 4; ii++) {
        float linv = 1.0f / l_s[ty * 4 + ii];
        int r = i * BLKQ + ty * 4 + ii;
        size_t base = (size_t)r * HID + h * DH;
#pragma unroll
        for (int half = 0; half < 2; half++) {
            int col0 = half * 64 + tx * 4;
            float o[4];
#pragma unroll
            for (int jj = 0; jj < 4; jj++) o[jj] = O[ii][half * 4 + jj] * linv;
            __half hh[4], hl[4];
#pragma unroll
            for (int jj = 0; jj < 4; jj++) {
                hh[jj] = __float2half_rn(o[jj]);
                hl[jj] = __float2half_rn(o[jj] - __half2float(hh[jj]));
            }
            *(__half2*)&g_oa_hi[base + col0]     = __halves2half2(hh[0], hh[1]);
            *(__half2*)&g_oa_hi[base + col0 + 2] = __halves2half2(hh[2], hh[3]);
            *(__half2*)&g_oa_lo[base + col0]     = __halves2half2(hl[0], hl[1]);
            *(__half2*)&g_oa_lo[base + col0 + 2] = __halves2half2(hl[2], hl[3]);
        }
    }
}

// ---------------- launch ----------------
extern "C" void kernel_launch(void* const* d_in, const int* in_sizes, int n_in,
                              void* d_out, int out_size)
{
    const float* hs  = (const float*)d_in[0];
    const int*   pos = (const int*)d_in[1];
    const float* Wq  = (const float*)d_in[2];
    const float* Wk  = (const float*)d_in[3];
    const float* Wv  = (const float*)d_in[4];
    const float* Wo  = (const float*)d_in[5];
    const float* Hm  = (const float*)d_in[6];
    float* out = (float*)d_out;

    float *qkv, *Sq, *Sk;
    __half *ha_hi, *ha_lo, *oa_hi, *oa_lo;
    __half2 *wb_hi, *wb_lo, *wob_hi, *wob_lo;
    cudaGetSymbolAddress((void**)&qkv,    g_qkv);
    cudaGetSymbolAddress((void**)&Sq,     g_Sq);
    cudaGetSymbolAddress((void**)&Sk,     g_Sk);
    cudaGetSymbolAddress((void**)&ha_hi,  g_ha_hi);
    cudaGetSymbolAddress((void**)&ha_lo,  g_ha_lo);
    cudaGetSymbolAddress((void**)&oa_hi,  g_oa_hi);
    cudaGetSymbolAddress((void**)&oa_lo,  g_oa_lo);
    cudaGetSymbolAddress((void**)&wb_hi,  g_wb_hi);
    cudaGetSymbolAddress((void**)&wb_lo,  g_wb_lo);
    cudaGetSymbolAddress((void**)&wob_hi, g_wob_hi);
    cudaGetSymbolAddress((void**)&wob_lo, g_wob_lo);

    cudaFuncSetAttribute(gemm_fp16_kernel, cudaFuncAttributeMaxDynamicSharedMemorySize,
                         GEMM_SMEM_BYTES);

    // operand prep
    split_a_kernel<<<SEQ * HID / 256, 256>>>(hs);
    pack_split_w_kernel<<<dim3(QKVN / 256, HID / 2), 256>>>(Wq, Wk, Wv);
    split_wo_kernel<<<dim3(HID / 256, HID / 2), 256>>>(Wo);

    // fused QKV projection (fp16 3-pass tensor GEMM)
    gemm_fp16_kernel<<<dim3(QKVN / 128, SEQ / 128), 256, GEMM_SMEM_BYTES>>>(
        ha_hi, ha_lo, wb_hi, wb_lo, qkv, SEQ, QKVN, HID);

    // RoPE
    invf_kernel<<<1, 64>>>();
    rope_table_kernel<<<SEQ, 64>>>(pos);
    rope_kernel<<<dim3(SEQ, NH), DH>>>(qkv, QKVN);            // q columns [0,2048)
    rope_kernel<<<dim3(SEQ, NKV), DH>>>(qkv + 2048, QKVN);    // k columns [2048,2560)

    // sketches
    sketch_kernel<<<dim3(NBLK, NH), DH>>>(qkv, Hm, Sq, QKVN);
    sketch_kernel<<<dim3(NBLK, NKV), DH>>>(qkv + 2048, Hm, Sk, QKVN);

    // block scores + top-k
    topk_kernel<<<dim3(NBLK, NH), 64>>>();

    // sparse attention (emits fp16 split planes)
    cudaFuncSetAttribute(attn_kernel, cudaFuncAttributeMaxDynamicSharedMemorySize, ATT_SMEM_BYTES);
    attn_kernel<<<dim3(NBLK, NH), 256, ATT_SMEM_BYTES>>>();

    // output projection (fp16 3-pass tensor GEMM)
    gemm_fp16_kernel<<<dim3(HID / 128, SEQ / 128), 256, GEMM_SMEM_BYTES>>>(
        oa_hi, oa_lo, wob_hi, wob_lo, out, SEQ, HID, HID);
}

// round 12
// speedup vs baseline: 3.5758x; 1.5576x over previous
#include <cuda_runtime.h>
#include <cuda_fp16.h>
#include <math.h>
#include <stdint.h>

// ---------------- problem constants ----------------
#define SEQ   4096
#define HID   2048
#define NH    16
#define NKV   4
#define DH    128
#define BLKQ  64
#define NBLK  64
#define MSK   32
#define KTOP  8
#define QKVN  3072          // fused QKV output columns (2048 q | 512 k | 512 v)

#define NEGV  (-1000000000.0f)

// ---------------- scratch (device globals; no allocation allowed) ----------------
__device__ float  g_qkv[SEQ * QKVN];         // fused q|k|v fp32, layout [s][3072]
__device__ __half g_ha_hi[SEQ * HID];        // hidden_states hi plane [s][k]
__device__ __half g_ha_lo[SEQ * HID];        // hidden_states lo plane
__device__ __half2 g_wb_hi[(HID/2) * QKVN];  // packed W_qkv hi, k-pair interleaved [k2][n]
__device__ __half2 g_wb_lo[(HID/2) * QKVN];
__device__ __half g_oa_hi[SEQ * HID];        // attention-out hi plane [s][n]
__device__ __half g_oa_lo[SEQ * HID];
__device__ __half2 g_wob_hi[(HID/2) * HID];  // Wo hi, k-pair interleaved [k2][n]
__device__ __half2 g_wob_lo[(HID/2) * HID];
__device__ float  g_Sq[NH * NBLK * MSK];
__device__ float  g_Sk[NKV * NBLK * MSK];
__device__ int    g_topk[NH * NBLK * KTOP];
__device__ float  g_cos[SEQ * 64];
__device__ float  g_sin[SEQ * 64];
__device__ double g_invf[64];

// ---------------- common fp16 helpers ----------------
__device__ __forceinline__ uint32_t smem_u32(const void* p) {
    uint32_t a;
    asm("{ .reg .u64 t; cvta.to.shared.u64 t, %1; cvt.u32.u64 %0, t; }" : "=r"(a) : "l"(p));
    return a;
}
__device__ __forceinline__ void mma16816(float c[4],
    uint32_t a0, uint32_t a1, uint32_t a2, uint32_t a3, uint32_t b0, uint32_t b1)
{
    asm volatile(
        "mma.sync.aligned.m16n8k16.row.col.f32.f16.f16.f32 "
        "{%0,%1,%2,%3}, {%4,%5,%6,%7}, {%8,%9}, {%0,%1,%2,%3};"
        : "+f"(c[0]), "+f"(c[1]), "+f"(c[2]), "+f"(c[3])
        : "r"(a0), "r"(a1), "r"(a2), "r"(a3), "r"(b0), "r"(b1));
}
// pack pair (x->lo, y->hi) into fp16x2 word; also residual word
__device__ __forceinline__ uint32_t h2u(float x, float y) {
    __half2 h = __halves2half2(__float2half_rn(x), __float2half_rn(y));
    return *(uint32_t*)&h;
}
__device__ __forceinline__ void split2(float x, float y, uint32_t& H, uint32_t& L) {
    __half hx = __float2half_rn(x), hy = __float2half_rn(y);
    __half2 hh = __halves2half2(hx, hy);
    H = *(uint32_t*)&hh;
    __half2 ll = __halves2half2(__float2half_rn(x - __half2float(hx)),
                                __float2half_rn(y - __half2float(hy)));
    L = *(uint32_t*)&ll;
}

// =======================================================================
// fp16 split GEMM (3-pass): unchanged from R7 (verified)
// =======================================================================
#define A_STR2 20
#define B_STR2 136
#define A_PLANE_W (128 * A_STR2)
#define B_PLANE_W (16 * B_STR2)
#define STAGE_W   (2 * A_PLANE_W + 2 * B_PLANE_W)
#define GEMM_SMEM_BYTES (2 * STAGE_W * 4)

#define CP16(dst, src) \
    asm volatile("cp.async.cg.shared.global [%0], [%1], 16;" :: "r"(dst), "l"(src))
#define CP_COMMIT() asm volatile("cp.async.commit_group;")
#define CP_WAIT1()  asm volatile("cp.async.wait_group 1;")

__global__ __launch_bounds__(256, 2) void gemm_fp16_kernel(
    const __half* __restrict__ Ah, const __half* __restrict__ Al,
    const __half2* __restrict__ Bh, const __half2* __restrict__ Bl,
    float* __restrict__ C, int M, int N, int K)
{
    extern __shared__ uint32_t smw[];
    const uint32_t smb = smem_u32(smw);

    const int bx = blockIdx.x * 128;
    const int by = blockIdx.y * 128;
    const int tid  = threadIdx.x;
    const int warp = tid >> 5;
    const int lane = tid & 31;
    const int g    = lane >> 2;
    const int tig  = lane & 3;
    const int warp_m = (warp & 1) * 64;
    const int warp_n = (warp >> 1) * 32;

    const int NIT = K / 32;
    const int ar = tid >> 2;
    const int ac = (tid & 3) * 16;
    const int bk = tid >> 5;
    const int bn = (tid & 31) * 16;

    auto load_stage = [&](int it, int s) {
        const int kt = it * 32;
        const uint32_t base = smb + (uint32_t)s * (STAGE_W * 4);
        {
            const char* sh = (const char*)(Ah + (size_t)(by + ar) * K + kt);
            const char* sl = (const char*)(Al + (size_t)(by + ar) * K + kt);
            CP16(base + ar * 80 + ac, sh + ac);
            CP16(base + A_PLANE_W * 4 + ar * 80 + ac, sl + ac);
            const char* sh2 = (const char*)(Ah + (size_t)(by + ar + 64) * K + kt);
            const char* sl2 = (const char*)(Al + (size_t)(by + ar + 64) * K + kt);
            CP16(base + (ar + 64) * 80 + ac, sh2 + ac);
            CP16(base + A_PLANE_W * 4 + (ar + 64) * 80 + ac, sl2 + ac);
        }
        {
            const uint32_t bb = base + 2 * A_PLANE_W * 4;
            const char* sh = (const char*)(Bh + (size_t)(kt / 2 + bk) * N + bx);
            const char* sl = (const char*)(Bl + (size_t)(kt / 2 + bk) * N + bx);
            CP16(bb + bk * 544 + bn, sh + bn);
            CP16(bb + B_PLANE_W * 4 + bk * 544 + bn, sl + bn);
            const char* sh2 = (const char*)(Bh + (size_t)(kt / 2 + bk + 8) * N + bx);
            const char* sl2 = (const char*)(Bl + (size_t)(kt / 2 + bk + 8) * N + bx);
            CP16(bb + (bk + 8) * 544 + bn, sh2 + bn);
            CP16(bb + B_PLANE_W * 4 + (bk + 8) * 544 + bn, sl2 + bn);
        }
    };

    float acc[4][4][4];
#pragma unroll
    for (int mt = 0; mt < 4; mt++)
#pragma unroll
        for (int nt = 0; nt < 4; nt++)
#pragma unroll
            for (int r = 0; r < 4; r++) acc[mt][nt][r] = 0.0f;

    load_stage(0, 0); CP_COMMIT();
    load_stage(1, 1); CP_COMMIT();

    for (int it = 0; it < NIT; ++it) {
        CP_WAIT1();
        __syncthreads();

        const uint32_t* st = smw + (it & 1) * STAGE_W;
        const uint32_t* AH = st;
        const uint32_t* AL = st + A_PLANE_W;
        const uint32_t* BH = st + 2 * A_PLANE_W;
        const uint32_t* BL = BH + B_PLANE_W;

#pragma unroll
        for (int kk = 0; kk < 2; ++kk) {
            uint32_t a[4][4], bh[4][2], bl[4][2];
#pragma unroll
            for (int nt = 0; nt < 4; nt++) {
                int n = warp_n + nt * 8 + g;
                bh[nt][0] = BH[(kk * 8 + tig) * B_STR2 + n];
                bh[nt][1] = BH[(kk * 8 + tig + 4) * B_STR2 + n];
                bl[nt][0] = BL[(kk * 8 + tig) * B_STR2 + n];
                bl[nt][1] = BL[(kk * 8 + tig + 4) * B_STR2 + n];
            }
#pragma unroll
            for (int mt = 0; mt < 4; mt++) {
                int row = warp_m + mt * 16 + g;
                a[mt][0] = AH[row * A_STR2 + kk * 8 + tig];
                a[mt][1] = AH[(row + 8) * A_STR2 + kk * 8 + tig];
                a[mt][2] = AH[row * A_STR2 + kk * 8 + tig + 4];
                a[mt][3] = AH[(row + 8) * A_STR2 + kk * 8 + tig + 4];
            }
#pragma unroll
            for (int mt = 0; mt < 4; mt++)
#pragma unroll
                for (int nt = 0; nt < 4; nt++)
                    mma16816(acc[mt][nt], a[mt][0], a[mt][1], a[mt][2], a[mt][3],
                             bh[nt][0], bh[nt][1]);
#pragma unroll
            for (int mt = 0; mt < 4; mt++)
#pragma unroll
                for (int nt = 0; nt < 4; nt++)
                    mma16816(acc[mt][nt], a[mt][0], a[mt][1], a[mt][2], a[mt][3],
                             bl[nt][0], bl[nt][1]);
#pragma unroll
            for (int mt = 0; mt < 4; mt++) {
                int row = warp_m + mt * 16 + g;
                a[mt][0] = AL[row * A_STR2 + kk * 8 + tig];
                a[mt][1] = AL[(row + 8) * A_STR2 + kk * 8 + tig];
                a[mt][2] = AL[row * A_STR2 + kk * 8 + tig + 4];
                a[mt][3] = AL[(row + 8) * A_STR2 + kk * 8 + tig + 4];
            }
#pragma unroll
            for (int mt = 0; mt < 4; mt++)
#pragma unroll
                for (int nt = 0; nt < 4; nt++)
                    mma16816(acc[mt][nt], a[mt][0], a[mt][1], a[mt][2], a[mt][3],
                             bh[nt][0], bh[nt][1]);
        }
        __syncthreads();
        if (it + 2 < NIT) load_stage(it + 2, it & 1);
        CP_COMMIT();
    }

#pragma unroll
    for (int mt = 0; mt < 4; mt++) {
#pragma unroll
        for (int nt = 0; nt < 4; nt++) {
            int row = by + warp_m + mt * 16 + g;
            int col = bx + warp_n + nt * 8 + 2 * tig;
            *(float2*)&C[(size_t)row * N + col]       = make_float2(acc[mt][nt][0], acc[mt][nt][1]);
            *(float2*)&C[(size_t)(row + 8) * N + col] = make_float2(acc[mt][nt][2], acc[mt][nt][3]);
        }
    }
}

// ---------------- operand prep kernels ----------------
__global__ void split_a_kernel(const float* __restrict__ src)
{
    int i = blockIdx.x * 256 + threadIdx.x;
    float x = src[i];
    __half h = __float2half_rn(x);
    g_ha_hi[i] = h;
    g_ha_lo[i] = __float2half_rn(x - __half2float(h));
}

__global__ void pack_split_w_kernel(const float* __restrict__ Wq,
                                    const float* __restrict__ Wk,
                                    const float* __restrict__ Wv)
{
    int k2 = blockIdx.y;
    int j  = blockIdx.x * 256 + threadIdx.x;
    const float* W; int col, width;
    if (j < 2048)      { W = Wq; col = j;        width = 2048; }
    else if (j < 2560) { W = Wk; col = j - 2048; width = 512;  }
    else               { W = Wv; col = j - 2560; width = 512;  }
    float x0 = W[(size_t)(2 * k2) * width + col];
    float x1 = W[(size_t)(2 * k2 + 1) * width + col];
    uint32_t H, L;
    split2(x0, x1, H, L);
    g_wb_hi[(size_t)k2 * QKVN + j] = *(__half2*)&H;
    g_wb_lo[(size_t)k2 * QKVN + j] = *(__half2*)&L;
}

__global__ void split_wo_kernel(const float* __restrict__ Wo)
{
    int k2 = blockIdx.y;
    int n  = blockIdx.x * 256 + threadIdx.x;
    float x0 = Wo[(size_t)(2 * k2) * HID + n];
    float x1 = Wo[(size_t)(2 * k2 + 1) * HID + n];
    uint32_t H, L;
    split2(x0, x1, H, L);
    g_wob_hi[(size_t)k2 * HID + n] = *(__half2*)&H;
    g_wob_lo[(size_t)k2 * HID + n] = *(__half2*)&L;
}

// ---------------- RoPE tables ----------------
__global__ void invf_kernel()
{
    int j = threadIdx.x;
    g_invf[j] = pow(10000.0, -(double)(2 * j) / 128.0);
}

__global__ void rope_table_kernel(const int* __restrict__ pos)
{
    int s = blockIdx.x;
    int j = threadIdx.x;
    double ang = (double)pos[s] * g_invf[j];
    double r = fmod(ang, 6.283185307179586476925286766559);
    float sv, cv;
    sincosf((float)r, &sv, &cv);
    g_cos[s * 64 + j] = cv;
    g_sin[s * 64 + j] = sv;
}

__global__ void rope_kernel(float* __restrict__ buf, int stride)
{
    int s = blockIdx.x;
    int h = blockIdx.y;
    int d = threadIdx.x;
    __shared__ float row[DH];
    float x = buf[(size_t)s * stride + h * DH + d];
    row[d] = x;
    __syncthreads();
    float part = (d < 64) ? -row[d + 64] : row[d - 64];
    float c  = g_cos[s * 64 + (d & 63)];
    float sn = g_sin[s * 64 + (d & 63)];
    buf[(size_t)s * stride + h * DH + d] = x * c + part * sn;
}

// ---------------- sketch ----------------
__global__ void sketch_kernel(const float* __restrict__ buf, const float* __restrict__ Hm,
                              float* __restrict__ Sout, int stride)
{
    int n = blockIdx.x;
    int h = blockIdx.y;
    int d = threadIdx.x;
    __shared__ float mv[DH];
    float sum = 0.0f;
#pragma unroll 8
    for (int r = 0; r < BLKQ; r++)
        sum += buf[(size_t)(n * BLKQ + r) * stride + h * DH + d];
    mv[d] = sum * (1.0f / 64.0f);
    __syncthreads();
    if (d < MSK) {
        float acc = 0.0f;
#pragma unroll 8
        for (int dd = 0; dd < DH; dd++)
            acc += mv[dd] * Hm[dd * MSK + d];
        Sout[(h * NBLK + n) * MSK + d] = acc;
    }
}

// ---------------- block-score + top-k ----------------
__global__ void topk_kernel()
{
    int i = blockIdx.x;
    int h = blockIdx.y;
    int j = threadIdx.x;
    __shared__ float bs[NBLK];

    float val;
    if (j > i) {
        val = NEGV;
    } else {
        const float* sq = &g_Sq[(h * NBLK + i) * MSK];
        const float* sk = &g_Sk[((h >> 2) * NBLK + j) * MSK];
        float acc = 0.0f;
#pragma unroll
        for (int m = 0; m < MSK; m++) acc += sq[m] * sk[m];
        val = acc;
    }
    if (j == i) val = 1000000000.0f;
    bs[j] = val;
    __syncthreads();

    if (j == 0) {
        for (int t = 0; t < KTOP; t++) {
            float best = -INFINITY;
            int bi = 0;
            for (int c = 0; c < NBLK; c++) {
                if (bs[c] > best) { best = bs[c]; bi = c; }
            }
            g_topk[(h * NBLK + i) * KTOP + t] = bi;
            bs[bi] = -INFINITY;
        }
    }
}

// =======================================================================
// sparse flash attention via m16n8k16 HMMA (3-pass hi/lo splits)
// grid (NBLK, NH), 128 threads (4 warps, M-split 16 rows each).
// Scores computed in log2 domain (Q scale folds in log2(e)) -> exp2f.
// smem (words): Qh[64][68] Ql | Kh[64][73] Kl (V[32][136] x2 reuses K space)
// =======================================================================
#define AQ_STR 68
#define KS_STR 73
#define VS_STR 136
#define Q_PLANE (64 * AQ_STR)           // 4352
#define K_PLANE (64 * KS_STR)           // 4672
#define V_PLANE (32 * VS_STR)           // 4352
#define ATT_SMEM_W (2 * Q_PLANE + 2 * K_PLANE)   // 18048 words
#define ATT_SMEM_BYTES (ATT_SMEM_W * 4)          // 72192 B

__global__ __launch_bounds__(128) void attn_kernel()
{
    extern __shared__ uint32_t smw[];
    uint32_t* Qh = smw;
    uint32_t* Ql = smw + Q_PLANE;
    uint32_t* Kh = smw + 2 * Q_PLANE;
    uint32_t* Kl = Kh + K_PLANE;
    uint32_t* Vh = Kh;                  // reuse K space for V
    uint32_t* Vl = Kh + V_PLANE;

    const int i   = blockIdx.x;
    const int h   = blockIdx.y;
    const int kvh = h >> 2;
    const int t    = threadIdx.x;
    const int warp = t >> 5;
    const int lane = t & 31;
    const int g    = lane >> 2;
    const int tig  = lane & 3;
    const int wm   = warp * 16;

    // fold 1/sqrt(128) * log2(e) into Q -> scores in log2 domain
    const float QSCALE = 0.12753100795667498f;

    // ---- load Q (scaled, split) ----
    for (int idx = t; idx < 64 * 64; idx += 128) {
        int r  = idx >> 6;
        int k2 = idx & 63;
        float2 q = *(const float2*)&g_qkv[(size_t)(i * BLKQ + r) * QKVN + h * DH + 2 * k2];
        uint32_t H, L;
        split2(q.x * QSCALE, q.y * QSCALE, H, L);
        Qh[r * AQ_STR + k2] = H;
        Ql[r * AQ_STR + k2] = L;
    }

    float O[16][4];
#pragma unroll
    for (int nt = 0; nt < 16; nt++)
#pragma unroll
        for (int r = 0; r < 4; r++) O[nt][r] = 0.0f;

    float m0 = -INFINITY, m1 = -INFINITY, l0 = 0.0f, l1 = 0.0f;
    const int qp0 = i * BLKQ + wm + g;
    const int qp1 = qp0 + 8;

    for (int kb = 0; kb < KTOP; kb++) {
        const int j = g_topk[(h * NBLK + i) * KTOP + kb];

        __syncthreads();   // prior-iter PV reads (and initial Q stores) done
        // ---- load K: word(d2, c) = {K[c][2d2], K[c][2d2+1]} ----
        for (int idx = t; idx < 64 * 64; idx += 128) {
            int c  = idx >> 6;
            int d2 = idx & 63;
            float2 kv = *(const float2*)&g_qkv[(size_t)(j * BLKQ + c) * QKVN + 2048 + kvh * DH + 2 * d2];
            uint32_t H, L;
            split2(kv.x, kv.y, H, L);
            Kh[d2 * KS_STR + c] = H;
            Kl[d2 * KS_STR + c] = L;
        }
        __syncthreads();   // K (and Q) ready

        // ---- QK^T, 3-pass ----
        float acc[8][4];
#pragma unroll
        for (int nt = 0; nt < 8; nt++)
#pragma unroll
            for (int r = 0; r < 4; r++) acc[nt][r] = 0.0f;

#pragma unroll
        for (int ks = 0; ks < 8; ++ks) {
            int a0i = (wm + g) * AQ_STR + ks * 8 + tig;
            uint32_t ah0 = Qh[a0i], ah1 = Qh[a0i + 8 * AQ_STR];
            uint32_t ah2 = Qh[a0i + 4], ah3 = Qh[a0i + 8 * AQ_STR + 4];
            uint32_t al0 = Ql[a0i], al1 = Ql[a0i + 8 * AQ_STR];
            uint32_t al2 = Ql[a0i + 4], al3 = Ql[a0i + 8 * AQ_STR + 4];
#pragma unroll
            for (int nt = 0; nt < 8; ++nt) {
                int b0i = (ks * 8 + tig) * KS_STR + nt * 8 + g;
                int b1i = b0i + 4 * KS_STR;
                uint32_t bh0 = Kh[b0i], bh1 = Kh[b1i];
                uint32_t bl0 = Kl[b0i], bl1 = Kl[b1i];
                mma16816(acc[nt], ah0, ah1, ah2, ah3, bh0, bh1);
                mma16816(acc[nt], ah0, ah1, ah2, ah3, bl0, bl1);
                mma16816(acc[nt], al0, al1, al2, al3, bh0, bh1);
            }
        }

        // ---- mask + online softmax (log2 domain, register-resident) ----
        const int kbase = j * BLKQ;
#pragma unroll
        for (int nt = 0; nt < 8; ++nt) {
            int c0 = kbase + nt * 8 + 2 * tig;
            if (c0 > qp0)     acc[nt][0] = -INFINITY;
            if (c0 + 1 > qp0) acc[nt][1] = -INFINITY;
            if (c0 > qp1)     acc[nt][2] = -INFINITY;
            if (c0 + 1 > qp1) acc[nt][3] = -INFINITY;
        }
        float rm0 = -INFINITY, rm1 = -INFINITY;
#pragma unroll
        for (int nt = 0; nt < 8; ++nt) {
            rm0 = fmaxf(rm0, fmaxf(acc[nt][0], acc[nt][1]));
            rm1 = fmaxf(rm1, fmaxf(acc[nt][2], acc[nt][3]));
        }
        rm0 = fmaxf(rm0, __shfl_xor_sync(0xffffffffu, rm0, 1));
        rm0 = fmaxf(rm0, __shfl_xor_sync(0xffffffffu, rm0, 2));
        rm1 = fmaxf(rm1, __shfl_xor_sync(0xffffffffu, rm1, 1));
        rm1 = fmaxf(rm1, __shfl_xor_sync(0xffffffffu, rm1, 2));

        float mn0 = fmaxf(m0, rm0), mn1 = fmaxf(m1, rm1);
        float al0f = exp2f(m0 - mn0), al1f = exp2f(m1 - mn1);
        m0 = mn0; m1 = mn1;

        float s0 = 0.0f, s1 = 0.0f;
#pragma unroll
        for (int nt = 0; nt < 8; ++nt) {
            acc[nt][0] = exp2f(acc[nt][0] - mn0);
            acc[nt][1] = exp2f(acc[nt][1] - mn0);
            acc[nt][2] = exp2f(acc[nt][2] - mn1);
            acc[nt][3] = exp2f(acc[nt][3] - mn1);
            s0 += acc[nt][0] + acc[nt][1];
            s1 += acc[nt][2] + acc[nt][3];
        }
        s0 += __shfl_xor_sync(0xffffffffu, s0, 1);
        s0 += __shfl_xor_sync(0xffffffffu, s0, 2);
        s1 += __shfl_xor_sync(0xffffffffu, s1, 1);
        s1 += __shfl_xor_sync(0xffffffffu, s1, 2);
        l0 = l0 * al0f + s0;
        l1 = l1 * al1f + s1;

#pragma unroll
        for (int nt = 0; nt < 16; ++nt) {
            O[nt][0] *= al0f; O[nt][1] *= al0f;
            O[nt][2] *= al1f; O[nt][3] *= al1f;
        }

        __syncthreads();   // all warps done reading K
        // ---- load V: word(c2, dd) = {V[2c2][dd], V[2c2+1][dd]} ----
        for (int idx = t; idx < 32 * 128; idx += 128) {
            int c2 = idx >> 7;
            int dd = idx & 127;
            size_t base = (size_t)(j * BLKQ + 2 * c2) * QKVN + 2560 + kvh * DH + dd;
            float v0 = g_qkv[base];
            float v1 = g_qkv[base + QKVN];
            uint32_t H, L;
            split2(v0, v1, H, L);
            Vh[c2 * VS_STR + dd] = H;
            Vl[c2 * VS_STR + dd] = L;
        }
        __syncthreads();   // V ready

        // ---- PV, 3-pass (P fragments straight from QK accumulator layout) ----
#pragma unroll
        for (int kk = 0; kk < 4; ++kk) {
            uint32_t ah0, ah1, ah2, ah3, al0_, al1_, al2_, al3_;
            split2(acc[2 * kk][0],     acc[2 * kk][1],     ah0, al0_);
            split2(acc[2 * kk][2],     acc[2 * kk][3],     ah1, al1_);
            split2(acc[2 * kk + 1][0], acc[2 * kk + 1][1], ah2, al2_);
            split2(acc[2 * kk + 1][2], acc[2 * kk + 1][3], ah3, al3_);
#pragma unroll
            for (int nt = 0; nt < 16; ++nt) {
                int b0i = (kk * 8 + tig) * VS_STR + nt * 8 + g;
                int b1i = b0i + 4 * VS_STR;
                uint32_t bh0 = Vh[b0i], bh1 = Vh[b1i];
                uint32_t bl0 = Vl[b0i], bl1 = Vl[b1i];
                mma16816(O[nt], ah0, ah1, ah2, ah3, bh0, bh1);
                mma16816(O[nt], al0_, al1_, al2_, al3_, bh0, bh1);
                mma16816(O[nt], ah0, ah1, ah2, ah3, bl0, bl1);
            }
        }
    }

    // ---- epilogue: divide by l, write fp16 split planes for Wo GEMM ----
    float inv0 = 1.0f / l0, inv1 = 1.0f / l1;
    int row0 = i * BLKQ + wm + g;
    int row1 = row0 + 8;
#pragma unroll
    for (int nt = 0; nt < 16; ++nt) {
        int d0 = nt * 8 + 2 * tig;
        uint32_t H, L;
        split2(O[nt][0] * inv0, O[nt][1] * inv0, H, L);
        *(uint32_t*)&g_oa_hi[(size_t)row0 * HID + h * DH + d0] = H;
        *(uint32_t*)&g_oa_lo[(size_t)row0 * HID + h * DH + d0] = L;
        split2(O[nt][2] * inv1, O[nt][3] * inv1, H, L);
        *(uint32_t*)&g_oa_hi[(size_t)row1 * HID + h * DH + d0] = H;
        *(uint32_t*)&g_oa_lo[(size_t)row1 * HID + h * DH + d0] = L;
    }
}

// ---------------- launch ----------------
extern "C" void kernel_launch(void* const* d_in, const int* in_sizes, int n_in,
                              void* d_out, int out_size)
{
    const float* hs  = (const float*)d_in[0];
    const int*   pos = (const int*)d_in[1];
    const float* Wq  = (const float*)d_in[2];
    const float* Wk  = (const float*)d_in[3];
    const float* Wv  = (const float*)d_in[4];
    const float* Wo  = (const float*)d_in[5];
    const float* Hm  = (const float*)d_in[6];
    float* out = (float*)d_out;

    float *qkv, *Sq, *Sk;
    __half *ha_hi, *ha_lo, *oa_hi, *oa_lo;
    __half2 *wb_hi, *wb_lo, *wob_hi, *wob_lo;
    cudaGetSymbolAddress((void**)&qkv,    g_qkv);
    cudaGetSymbolAddress((void**)&Sq,     g_Sq);
    cudaGetSymbolAddress((void**)&Sk,     g_Sk);
    cudaGetSymbolAddress((void**)&ha_hi,  g_ha_hi);
    cudaGetSymbolAddress((void**)&ha_lo,  g_ha_lo);
    cudaGetSymbolAddress((void**)&oa_hi,  g_oa_hi);
    cudaGetSymbolAddress((void**)&oa_lo,  g_oa_lo);
    cudaGetSymbolAddress((void**)&wb_hi,  g_wb_hi);
    cudaGetSymbolAddress((void**)&wb_lo,  g_wb_lo);
    cudaGetSymbolAddress((void**)&wob_hi, g_wob_hi);
    cudaGetSymbolAddress((void**)&wob_lo, g_wob_lo);

    cudaFuncSetAttribute(gemm_fp16_kernel, cudaFuncAttributeMaxDynamicSharedMemorySize,
                         GEMM_SMEM_BYTES);
    cudaFuncSetAttribute(attn_kernel, cudaFuncAttributeMaxDynamicSharedMemorySize,
                         ATT_SMEM_BYTES);

    // operand prep
    split_a_kernel<<<SEQ * HID / 256, 256>>>(hs);
    pack_split_w_kernel<<<dim3(QKVN / 256, HID / 2), 256>>>(Wq, Wk, Wv);
    split_wo_kernel<<<dim3(HID / 256, HID / 2), 256>>>(Wo);

    // fused QKV projection
    gemm_fp16_kernel<<<dim3(QKVN / 128, SEQ / 128), 256, GEMM_SMEM_BYTES>>>(
        ha_hi, ha_lo, wb_hi, wb_lo, qkv, SEQ, QKVN, HID);

    // RoPE
    invf_kernel<<<1, 64>>>();
    rope_table_kernel<<<SEQ, 64>>>(pos);
    rope_kernel<<<dim3(SEQ, NH), DH>>>(qkv, QKVN);
    rope_kernel<<<dim3(SEQ, NKV), DH>>>(qkv + 2048, QKVN);

    // sketches
    sketch_kernel<<<dim3(NBLK, NH), DH>>>(qkv, Hm, Sq, QKVN);
    sketch_kernel<<<dim3(NBLK, NKV), DH>>>(qkv + 2048, Hm, Sk, QKVN);

    // block scores + top-k
    topk_kernel<<<dim3(NBLK, NH), 64>>>();

    // sparse attention (tensor-core, emits fp16 split planes)
    attn_kernel<<<dim3(NBLK, NH), 128, ATT_SMEM_BYTES>>>();

    // output projection
    gemm_fp16_kernel<<<dim3(HID / 128, SEQ / 128), 256, GEMM_SMEM_BYTES>>>(
        oa_hi, oa_lo, wob_hi, wob_lo, out, SEQ, HID, HID);
}